// round 6
// baseline (speedup 1.0000x reference)
#include <cuda_runtime.h>
#include <cuda_bf16.h>

#define N_NODES 50000
#define N_EDGES 800000
#define IN_CH   64
#define OUT_CH  128
#define F_TOT   192     // IN_CH * 3 powers
#define MAX_DEG 64      // P(Poisson(16) > 64) ~ 1e-18 over all nodes

// Scratch (device globals: allocation-free rule).
// RULE (round-3/4 bug): NEVER pass these as kernel arguments from host code —
// the host shadow address gets passed and on GB300 (ATS) device writes land in
// HOST memory silently. Access from device code only.
__device__ float g_h1[N_NODES * IN_CH];        // 12.8 MB
__device__ float g_h2[N_NODES * IN_CH];        // 12.8 MB
__device__ float g_Wd[F_TOT * OUT_CH * 2];     // duplicated packed W: [k][o*2+{0,1}]
__device__ int   g_cnt[N_NODES];               // per-dst degree / fill cursor
__device__ int   g_srcs[N_NODES * MAX_DEG];    // bucketed src lists (12.8 MB)
__device__ int   g_is64;                       // 1 if edge_index is int64

// ---------------------------------------------------------------------------
// Zero counters + (block 0) dtype probe: int64 data (values < 50000, LE) has
// all odd int32 words == 0; random int32 indices essentially never do.
// ---------------------------------------------------------------------------
__global__ void zero_detect_kernel(const int* __restrict__ ei32) {
    int i = blockIdx.x * blockDim.x + threadIdx.x;
    if (i < N_NODES) g_cnt[i] = 0;
    if (blockIdx.x == 0) {
        int v = ei32[2 * threadIdx.x + 1];
        int any_nonzero = __syncthreads_or(v != 0);
        if (threadIdx.x == 0) g_is64 = !any_nonzero;
    }
}

__device__ __forceinline__ void load_edge(const int* __restrict__ ei32,
                                          int e, int is64, int& s, int& d) {
    if (is64) { s = ei32[2 * e];  d = ei32[2 * (N_EDGES + e)]; }
    else      { s = ei32[e];      d = ei32[N_EDGES + e]; }
}

// ---------------------------------------------------------------------------
// CSR-bucket fill: scatter edge srcs into dst buckets.
// ---------------------------------------------------------------------------
__global__ void fill_kernel(const int* __restrict__ ei32) {
    int e = blockIdx.x * blockDim.x + threadIdx.x;
    if (e >= N_EDGES) return;
    int s, d;
    load_edge(ei32, e, g_is64, s, d);
    int pos = atomicAdd(&g_cnt[d], 1);
    if (pos < MAX_DEG) g_srcs[d * MAX_DEG + pos] = s;
}

// ---------------------------------------------------------------------------
// Gather hop (unchanged from round-5 pass): 16 threads/node, float4 lanes.
// hop==0: x -> g_h1 ; hop==1: g_h1 -> g_h2  (selected IN DEVICE CODE)
// ---------------------------------------------------------------------------
__global__ __launch_bounds__(256)
void gather_kernel(const float* __restrict__ x, int hop) {
    int idx = blockIdx.x * blockDim.x + threadIdx.x;
    int n = idx >> 4;
    int c = (idx & 15) << 2;
    if (n >= N_NODES) return;

    const float* src_feat = (hop == 0) ? x : g_h1;
    float*       dst_feat = (hop == 0) ? g_h1 : g_h2;

    int deg = g_cnt[n];
    if (deg > MAX_DEG) deg = MAX_DEG;
    const int* lst = g_srcs + n * MAX_DEG;

    float4 acc = make_float4(0.f, 0.f, 0.f, 0.f);
    int i = 0;
    for (; i + 4 <= deg; i += 4) {
        int s0 = lst[i], s1 = lst[i + 1], s2 = lst[i + 2], s3 = lst[i + 3];
        float4 v0 = *reinterpret_cast<const float4*>(src_feat + (size_t)s0 * IN_CH + c);
        float4 v1 = *reinterpret_cast<const float4*>(src_feat + (size_t)s1 * IN_CH + c);
        float4 v2 = *reinterpret_cast<const float4*>(src_feat + (size_t)s2 * IN_CH + c);
        float4 v3 = *reinterpret_cast<const float4*>(src_feat + (size_t)s3 * IN_CH + c);
        acc.x += (v0.x + v1.x) + (v2.x + v3.x);
        acc.y += (v0.y + v1.y) + (v2.y + v3.y);
        acc.z += (v0.z + v1.z) + (v2.z + v3.z);
        acc.w += (v0.w + v1.w) + (v2.w + v3.w);
    }
    for (; i < deg; i++) {
        int s = lst[i];
        float4 v = *reinterpret_cast<const float4*>(src_feat + (size_t)s * IN_CH + c);
        acc.x += v.x; acc.y += v.y; acc.z += v.z; acc.w += v.w;
    }
    *reinterpret_cast<float4*>(dst_feat + (size_t)n * IN_CH + c) = acc;
}

// ---------------------------------------------------------------------------
// Transpose + duplicate W [OUT_CH][F_TOT] -> g_Wd [F_TOT][OUT_CH*2]:
// g_Wd[k][2o] = g_Wd[k][2o+1] = W[o][k]   (packed f32x2 weight operands)
// ---------------------------------------------------------------------------
__global__ void transpose_W_kernel(const float* __restrict__ W) {
    int i = blockIdx.x * blockDim.x + threadIdx.x;
    if (i < OUT_CH * F_TOT) {
        int o = i / F_TOT;
        int k = i - o * F_TOT;
        float v = W[i];
        g_Wd[k * (OUT_CH * 2) + o * 2]     = v;
        g_Wd[k * (OUT_CH * 2) + o * 2 + 1] = v;
    }
}

// ---------------------------------------------------------------------------
// f32x2 GEMM + bias: out[n,o] = b[o] + sum_k feat[n,k] * W[o,k]
// Block: 512 threads, 128 nodes x 128 outs, 2 blocks/SM (smem = feats only).
// Thread: 4 node-pairs x 4 outs = 16 f32x2 accumulators.
// Weights: pre-duplicated pairs from g_Wd via 2x LDG.128 per k (L1/L2-hot);
// no pack MOVs, no weight LDS.
// ---------------------------------------------------------------------------
#define F2_PITCH 130
#define NODES_PER_BLK 128
#define GEMM_THREADS 512
#define GEMM_SMEM_BYTES (F_TOT * F2_PITCH * (int)sizeof(float))

static __device__ __forceinline__ unsigned long long pk(float lo, float hi) {
    unsigned long long r;
    asm("mov.b64 %0, {%1, %2};" : "=l"(r) : "f"(lo), "f"(hi));
    return r;
}
static __device__ __forceinline__ void upk(unsigned long long v, float& lo, float& hi) {
    asm("mov.b64 {%0, %1}, %2;" : "=f"(lo), "=f"(hi) : "l"(v));
}
static __device__ __forceinline__ void ffma2(unsigned long long& d,
                                             unsigned long long a,
                                             unsigned long long b) {
    asm("fma.rn.f32x2 %0, %1, %2, %0;" : "+l"(d) : "l"(a), "l"(b));
}

__global__ __launch_bounds__(GEMM_THREADS, 2)
void gemm_kernel(const float* __restrict__ x,
                 const float* __restrict__ b,
                 float* __restrict__ out) {
    extern __shared__ float fs2[];          // [192][130]: fs2[k*130 + n_local]

    const int tid  = threadIdx.x;
    const int base = blockIdx.x * NODES_PER_BLK;

    // Features, k-major: fs2[k][n] = concat(x,h1,h2)[base+n][k]
    for (int i = tid; i < NODES_PER_BLK * F_TOT; i += GEMM_THREADS) {
        int n = i / F_TOT;
        int k = i - n * F_TOT;
        int node = base + n;
        if (node >= N_NODES) node = N_NODES - 1;   // clamp; store is guarded
        float v;
        if (k < IN_CH)            v = x[(size_t)node * IN_CH + k];
        else if (k < 2 * IN_CH)   v = g_h1[(size_t)node * IN_CH + (k - IN_CH)];
        else                      v = g_h2[(size_t)node * IN_CH + (k - 2 * IN_CH)];
        fs2[k * F2_PITCH + n] = v;
    }
    __syncthreads();

    const int to = tid & 31;   // outs [to*4, to*4+4)
    const int tg = tid >> 5;   // node pairs [tg*4, tg*4+4)  (16 warps)

    unsigned long long acc[4][4];  // [pair j][out o]
    {
        float4 bias = *reinterpret_cast<const float4*>(b + to * 4);
        unsigned long long b0 = pk(bias.x, bias.x), b1 = pk(bias.y, bias.y);
        unsigned long long b2 = pk(bias.z, bias.z), b3 = pk(bias.w, bias.w);
        #pragma unroll
        for (int j = 0; j < 4; j++) {
            acc[j][0] = b0; acc[j][1] = b1; acc[j][2] = b2; acc[j][3] = b3;
        }
    }

    const float* wrow = g_Wd + to * 8;      // this thread's 4 duplicated pairs
    #pragma unroll 4
    for (int k = 0; k < F_TOT; k++) {
        // wd0..wd3: duplicated weight pairs, two 16B loads (L1/L2-resident)
        const ulonglong2 wp0 =
            *reinterpret_cast<const ulonglong2*>(wrow + (size_t)k * (OUT_CH * 2));
        const ulonglong2 wp1 =
            *reinterpret_cast<const ulonglong2*>(wrow + (size_t)k * (OUT_CH * 2) + 4);
        const float* frow = fs2 + k * F2_PITCH + tg * 8;  // 8B-aligned pairs
        #pragma unroll
        for (int j = 0; j < 4; j++) {
            unsigned long long f2 =
                *reinterpret_cast<const unsigned long long*>(frow + j * 2);
            ffma2(acc[j][0], f2, wp0.x);
            ffma2(acc[j][1], f2, wp0.y);
            ffma2(acc[j][2], f2, wp1.x);
            ffma2(acc[j][3], f2, wp1.y);
        }
    }

    #pragma unroll
    for (int j = 0; j < 4; j++) {
        float lo0, hi0, lo1, hi1, lo2, hi2, lo3, hi3;
        upk(acc[j][0], lo0, hi0); upk(acc[j][1], lo1, hi1);
        upk(acc[j][2], lo2, hi2); upk(acc[j][3], lo3, hi3);
        int n0 = base + (tg * 4 + j) * 2;
        if (n0 < N_NODES) {
            *reinterpret_cast<float4*>(out + (size_t)n0 * OUT_CH + to * 4) =
                make_float4(lo0, lo1, lo2, lo3);
        }
        if (n0 + 1 < N_NODES) {
            *reinterpret_cast<float4*>(out + (size_t)(n0 + 1) * OUT_CH + to * 4) =
                make_float4(hi0, hi1, hi2, hi3);
        }
    }
}

// ---------------------------------------------------------------------------
// Launch: zero+detect -> fill -> gather x2 -> transpose -> gemm  (6 launches)
// ---------------------------------------------------------------------------
extern "C" void kernel_launch(void* const* d_in, const int* in_sizes, int n_in,
                              void* d_out, int out_size) {
    const float*  x   = (const float*)d_in[0];
    const int*    ei  = (const int*)d_in[1];
    const float*  W   = (const float*)d_in[2];
    const float*  b   = (const float*)d_in[3];
    float*        out = (float*)d_out;

    cudaFuncSetAttribute(gemm_kernel,
                         cudaFuncAttributeMaxDynamicSharedMemorySize,
                         GEMM_SMEM_BYTES);

    zero_detect_kernel<<<(N_NODES + 1023) / 1024, 1024>>>(ei);
    fill_kernel<<<(N_EDGES + 255) / 256, 256>>>(ei);

    const int gthreads = N_NODES * 16;
    gather_kernel<<<(gthreads + 255) / 256, 256>>>(x, 0);
    gather_kernel<<<(gthreads + 255) / 256, 256>>>(x, 1);

    transpose_W_kernel<<<(OUT_CH * F_TOT + 255) / 256, 256>>>(W);

    const int gemm_blocks = (N_NODES + NODES_PER_BLK - 1) / NODES_PER_BLK;
    gemm_kernel<<<gemm_blocks, GEMM_THREADS, GEMM_SMEM_BYTES>>>(x, b, out);
}

// round 7
// speedup vs baseline: 1.3401x; 1.3401x over previous
#include <cuda_runtime.h>
#include <cuda_bf16.h>

#define N_NODES 50000
#define N_EDGES 800000
#define IN_CH   64
#define OUT_CH  128
#define F_TOT   192     // IN_CH * 3 powers
#define MAX_DEG 64      // P(Poisson(16) > 64) ~ 1e-18 over all nodes

// Scratch (device globals: allocation-free rule).
// RULE (round-3/4 bug): NEVER pass these as kernel arguments from host code —
// the host shadow address gets passed and on GB300 (ATS) device writes land in
// HOST memory silently. Access from device code only.
__device__ float g_h1[N_NODES * IN_CH];        // 12.8 MB
__device__ float g_h2[N_NODES * IN_CH];        // 12.8 MB
__device__ float g_Wt[F_TOT * OUT_CH];         // W transposed: [k][o]  (98 KB)
__device__ int   g_cnt[N_NODES];               // per-dst degree / fill cursor
__device__ int   g_srcs[N_NODES * MAX_DEG];    // bucketed src lists (12.8 MB)
__device__ int   g_is64;                       // 1 if edge_index is int64

// ---------------------------------------------------------------------------
// Zero counters + transpose W + (block 0) dtype probe.
// int64 data (values < 50000, LE) has all odd int32 words == 0.
// ---------------------------------------------------------------------------
__global__ void zero_detect_transpose_kernel(const int* __restrict__ ei32,
                                             const float* __restrict__ W) {
    int i = blockIdx.x * blockDim.x + threadIdx.x;
    if (i < N_NODES) g_cnt[i] = 0;
    if (i < OUT_CH * F_TOT) {
        int o = i / F_TOT;
        int k = i - o * F_TOT;
        g_Wt[k * OUT_CH + o] = W[i];
    }
    if (blockIdx.x == 0) {
        int v = ei32[2 * threadIdx.x + 1];
        int any_nonzero = __syncthreads_or(v != 0);
        if (threadIdx.x == 0) g_is64 = !any_nonzero;
    }
}

__device__ __forceinline__ void load_edge(const int* __restrict__ ei32,
                                          int e, int is64, int& s, int& d) {
    if (is64) { s = ei32[2 * e];  d = ei32[2 * (N_EDGES + e)]; }
    else      { s = ei32[e];      d = ei32[N_EDGES + e]; }
}

// ---------------------------------------------------------------------------
// CSR-bucket fill: scatter edge srcs into dst buckets.
// ---------------------------------------------------------------------------
__global__ void fill_kernel(const int* __restrict__ ei32) {
    int e = blockIdx.x * blockDim.x + threadIdx.x;
    if (e >= N_EDGES) return;
    int s, d;
    load_edge(ei32, e, g_is64, s, d);
    int pos = atomicAdd(&g_cnt[d], 1);
    if (pos < MAX_DEG) g_srcs[d * MAX_DEG + pos] = s;
}

// ---------------------------------------------------------------------------
// Gather hop (unchanged — 21.9us, near L2 floor): 16 threads/node.
// hop==0: x -> g_h1 ; hop==1: g_h1 -> g_h2  (selected IN DEVICE CODE)
// ---------------------------------------------------------------------------
__global__ __launch_bounds__(256)
void gather_kernel(const float* __restrict__ x, int hop) {
    int idx = blockIdx.x * blockDim.x + threadIdx.x;
    int n = idx >> 4;
    int c = (idx & 15) << 2;
    if (n >= N_NODES) return;

    const float* src_feat = (hop == 0) ? x : g_h1;
    float*       dst_feat = (hop == 0) ? g_h1 : g_h2;

    int deg = g_cnt[n];
    if (deg > MAX_DEG) deg = MAX_DEG;
    const int* lst = g_srcs + n * MAX_DEG;

    float4 acc = make_float4(0.f, 0.f, 0.f, 0.f);
    int i = 0;
    for (; i + 4 <= deg; i += 4) {
        int s0 = lst[i], s1 = lst[i + 1], s2 = lst[i + 2], s3 = lst[i + 3];
        float4 v0 = *reinterpret_cast<const float4*>(src_feat + (size_t)s0 * IN_CH + c);
        float4 v1 = *reinterpret_cast<const float4*>(src_feat + (size_t)s1 * IN_CH + c);
        float4 v2 = *reinterpret_cast<const float4*>(src_feat + (size_t)s2 * IN_CH + c);
        float4 v3 = *reinterpret_cast<const float4*>(src_feat + (size_t)s3 * IN_CH + c);
        acc.x += (v0.x + v1.x) + (v2.x + v3.x);
        acc.y += (v0.y + v1.y) + (v2.y + v3.y);
        acc.z += (v0.z + v1.z) + (v2.z + v3.z);
        acc.w += (v0.w + v1.w) + (v2.w + v3.w);
    }
    for (; i < deg; i++) {
        int s = lst[i];
        float4 v = *reinterpret_cast<const float4*>(src_feat + (size_t)s * IN_CH + c);
        acc.x += v.x; acc.y += v.y; acc.z += v.z; acc.w += v.w;
    }
    *reinterpret_cast<float4*>(dst_feat + (size_t)n * IN_CH + c) = acc;
}

// ---------------------------------------------------------------------------
// f32x2 GEMM + bias: out[n,o] = b[o] + sum_k feat[n,k] * W[o,k]
// Block: 256 threads, 64 nodes x 128 outs, 3 blocks/SM (smem 52KB feats only).
// Warp: 8 nodes (4 pairs) x 128 outs; thread: 4 pairs x 4 outs (16 f32x2 acc).
// Weights: LDG.128 from g_Wt (L1-resident, all warps share addresses) + pk.
// Features: 2x LDS.128 warp-broadcast per k (16B-aligned pitch 68).
// ---------------------------------------------------------------------------
#define F2_PITCH 68   // 68 floats = 272 B, 16B-multiple for LDS.128
#define NODES_PER_BLK 64
#define GEMM_THREADS 256
#define GEMM_SMEM_BYTES (F_TOT * F2_PITCH * (int)sizeof(float))

static __device__ __forceinline__ unsigned long long pk(float lo, float hi) {
    unsigned long long r;
    asm("mov.b64 %0, {%1, %2};" : "=l"(r) : "f"(lo), "f"(hi));
    return r;
}
static __device__ __forceinline__ void upk(unsigned long long v, float& lo, float& hi) {
    asm("mov.b64 {%0, %1}, %2;" : "=f"(lo), "=f"(hi) : "l"(v));
}
static __device__ __forceinline__ void ffma2(unsigned long long& d,
                                             unsigned long long a,
                                             unsigned long long b) {
    asm("fma.rn.f32x2 %0, %1, %2, %0;" : "+l"(d) : "l"(a), "l"(b));
}

__global__ __launch_bounds__(GEMM_THREADS, 3)
void gemm_kernel(const float* __restrict__ x,
                 const float* __restrict__ b,
                 float* __restrict__ out) {
    extern __shared__ float fs2[];          // [192][68]: fs2[k*68 + n_local]

    const int tid  = threadIdx.x;
    const int base = blockIdx.x * NODES_PER_BLK;

    // Stage features, k-major: fs2[k][n] = concat(x,h1,h2)[base+n][k]
    // (consecutive tid -> consecutive k: coalesced global reads)
    for (int i = tid; i < NODES_PER_BLK * F_TOT; i += GEMM_THREADS) {
        int n = i / F_TOT;
        int k = i - n * F_TOT;
        int node = base + n;
        if (node >= N_NODES) node = N_NODES - 1;   // clamp; store is guarded
        float v;
        if (k < IN_CH)            v = x[(size_t)node * IN_CH + k];
        else if (k < 2 * IN_CH)   v = g_h1[(size_t)node * IN_CH + (k - IN_CH)];
        else                      v = g_h2[(size_t)node * IN_CH + (k - 2 * IN_CH)];
        fs2[k * F2_PITCH + n] = v;
    }
    __syncthreads();

    const int to = tid & 31;   // outs [to*4, to*4+4)
    const int w  = tid >> 5;   // warp id: node pairs [w*4, w*4+4)  (8 warps)

    unsigned long long acc[4][4];  // [pair j][out o]
    {
        float4 bias = *reinterpret_cast<const float4*>(b + to * 4);
        unsigned long long b0 = pk(bias.x, bias.x), b1 = pk(bias.y, bias.y);
        unsigned long long b2 = pk(bias.z, bias.z), b3 = pk(bias.w, bias.w);
        #pragma unroll
        for (int j = 0; j < 4; j++) {
            acc[j][0] = b0; acc[j][1] = b1; acc[j][2] = b2; acc[j][3] = b3;
        }
    }

    const float* wrow = g_Wt + to * 4;         // this thread's 4 weights per k
    const float* frow0 = fs2 + w * 8;          // this warp's 8 nodes (4 pairs)
    #pragma unroll 4
    for (int k = 0; k < F_TOT; k++) {
        // Weights: one LDG.128 (same 512B across all warps -> L1-hot)
        float4 w4 = *reinterpret_cast<const float4*>(wrow + (size_t)k * OUT_CH);
        unsigned long long wd0 = pk(w4.x, w4.x);
        unsigned long long wd1 = pk(w4.y, w4.y);
        unsigned long long wd2 = pk(w4.z, w4.z);
        unsigned long long wd3 = pk(w4.w, w4.w);
        // Features: 4 pairs = 32B via 2x LDS.128 broadcast (16B-aligned)
        const float* frow = frow0 + k * F2_PITCH;
        ulonglong2 fa = *reinterpret_cast<const ulonglong2*>(frow);      // pairs 0,1
        ulonglong2 fb = *reinterpret_cast<const ulonglong2*>(frow + 4);  // pairs 2,3
        ffma2(acc[0][0], fa.x, wd0); ffma2(acc[0][1], fa.x, wd1);
        ffma2(acc[0][2], fa.x, wd2); ffma2(acc[0][3], fa.x, wd3);
        ffma2(acc[1][0], fa.y, wd0); ffma2(acc[1][1], fa.y, wd1);
        ffma2(acc[1][2], fa.y, wd2); ffma2(acc[1][3], fa.y, wd3);
        ffma2(acc[2][0], fb.x, wd0); ffma2(acc[2][1], fb.x, wd1);
        ffma2(acc[2][2], fb.x, wd2); ffma2(acc[2][3], fb.x, wd3);
        ffma2(acc[3][0], fb.y, wd0); ffma2(acc[3][1], fb.y, wd1);
        ffma2(acc[3][2], fb.y, wd2); ffma2(acc[3][3], fb.y, wd3);
    }

    #pragma unroll
    for (int j = 0; j < 4; j++) {
        float lo0, hi0, lo1, hi1, lo2, hi2, lo3, hi3;
        upk(acc[j][0], lo0, hi0); upk(acc[j][1], lo1, hi1);
        upk(acc[j][2], lo2, hi2); upk(acc[j][3], lo3, hi3);
        int n0 = base + (w * 4 + j) * 2;
        if (n0 < N_NODES) {
            *reinterpret_cast<float4*>(out + (size_t)n0 * OUT_CH + to * 4) =
                make_float4(lo0, lo1, lo2, lo3);
        }
        if (n0 + 1 < N_NODES) {
            *reinterpret_cast<float4*>(out + (size_t)(n0 + 1) * OUT_CH + to * 4) =
                make_float4(hi0, hi1, hi2, hi3);
        }
    }
}

// ---------------------------------------------------------------------------
// Launch: zero+detect+transpose -> fill -> gather x2 -> gemm  (5 launches)
// ---------------------------------------------------------------------------
extern "C" void kernel_launch(void* const* d_in, const int* in_sizes, int n_in,
                              void* d_out, int out_size) {
    const float*  x   = (const float*)d_in[0];
    const int*    ei  = (const int*)d_in[1];
    const float*  W   = (const float*)d_in[2];
    const float*  b   = (const float*)d_in[3];
    float*        out = (float*)d_out;

    cudaFuncSetAttribute(gemm_kernel,
                         cudaFuncAttributeMaxDynamicSharedMemorySize,
                         GEMM_SMEM_BYTES);

    zero_detect_transpose_kernel<<<(N_NODES + 1023) / 1024, 1024>>>(ei, W);
    fill_kernel<<<(N_EDGES + 255) / 256, 256>>>(ei);

    const int gthreads = N_NODES * 16;
    gather_kernel<<<(gthreads + 255) / 256, 256>>>(x, 0);
    gather_kernel<<<(gthreads + 255) / 256, 256>>>(x, 1);

    const int gemm_blocks = (N_NODES + NODES_PER_BLK - 1) / NODES_PER_BLK;
    gemm_kernel<<<gemm_blocks, GEMM_THREADS, GEMM_SMEM_BYTES>>>(x, b, out);
}

// round 8
// speedup vs baseline: 1.5392x; 1.1486x over previous
#include <cuda_runtime.h>
#include <cuda_bf16.h>

#define N_NODES 50000
#define N_EDGES 800000
#define IN_CH   64
#define OUT_CH  128
#define F_TOT   192     // IN_CH * 3 powers
#define MAX_DEG 64      // P(Poisson(16) > 64) ~ 1e-18 over all nodes

// Scratch (device globals: allocation-free rule).
// RULE (round-3/4 bug): NEVER pass these as kernel arguments from host code —
// the host shadow address gets passed and on GB300 (ATS) device writes land in
// HOST memory silently. Access from device code only.
__device__ float g_h1[N_NODES * IN_CH];        // 12.8 MB
__device__ float g_Wt[F_TOT * OUT_CH];         // W transposed: [k][o]  (98 KB)
__device__ int   g_cnt[N_NODES];               // per-dst degree / fill cursor
__device__ int   g_srcs[N_NODES * MAX_DEG];    // bucketed src lists (12.8 MB)
__device__ int   g_is64;                       // 1 if edge_index is int64

// ---------------------------------------------------------------------------
// Zero counters + transpose W + (block 0) dtype probe.
// int64 data (values < 50000, LE) has all odd int32 words == 0.
// ---------------------------------------------------------------------------
__global__ void zero_detect_transpose_kernel(const int* __restrict__ ei32,
                                             const float* __restrict__ W) {
    int i = blockIdx.x * blockDim.x + threadIdx.x;
    if (i < N_NODES) g_cnt[i] = 0;
    if (i < OUT_CH * F_TOT) {
        int o = i / F_TOT;
        int k = i - o * F_TOT;
        g_Wt[k * OUT_CH + o] = W[i];
    }
    if (blockIdx.x == 0) {
        int v = ei32[2 * threadIdx.x + 1];
        int any_nonzero = __syncthreads_or(v != 0);
        if (threadIdx.x == 0) g_is64 = !any_nonzero;
    }
}

__device__ __forceinline__ void load_edge(const int* __restrict__ ei32,
                                          int e, int is64, int& s, int& d) {
    if (is64) { s = ei32[2 * e];  d = ei32[2 * (N_EDGES + e)]; }
    else      { s = ei32[e];      d = ei32[N_EDGES + e]; }
}

// ---------------------------------------------------------------------------
// CSR-bucket fill: scatter edge srcs into dst buckets.
// ---------------------------------------------------------------------------
__global__ void fill_kernel(const int* __restrict__ ei32) {
    int e = blockIdx.x * blockDim.x + threadIdx.x;
    if (e >= N_EDGES) return;
    int s, d;
    load_edge(ei32, e, g_is64, s, d);
    int pos = atomicAdd(&g_cnt[d], 1);
    if (pos < MAX_DEG) g_srcs[d * MAX_DEG + pos] = s;
}

// ---------------------------------------------------------------------------
// Gather hop 1 only: g_h1[n] = sum over bucket srcs of x[s]. 16 thr/node.
// (hop 2 is fused into the GEMM below.)
// ---------------------------------------------------------------------------
__global__ __launch_bounds__(256)
void gather_kernel(const float* __restrict__ x) {
    int idx = blockIdx.x * blockDim.x + threadIdx.x;
    int n = idx >> 4;
    int c = (idx & 15) << 2;
    if (n >= N_NODES) return;

    int deg = g_cnt[n];
    if (deg > MAX_DEG) deg = MAX_DEG;
    const int* lst = g_srcs + n * MAX_DEG;

    float4 acc = make_float4(0.f, 0.f, 0.f, 0.f);
    int i = 0;
    for (; i + 4 <= deg; i += 4) {
        int s0 = lst[i], s1 = lst[i + 1], s2 = lst[i + 2], s3 = lst[i + 3];
        float4 v0 = *reinterpret_cast<const float4*>(x + (size_t)s0 * IN_CH + c);
        float4 v1 = *reinterpret_cast<const float4*>(x + (size_t)s1 * IN_CH + c);
        float4 v2 = *reinterpret_cast<const float4*>(x + (size_t)s2 * IN_CH + c);
        float4 v3 = *reinterpret_cast<const float4*>(x + (size_t)s3 * IN_CH + c);
        acc.x += (v0.x + v1.x) + (v2.x + v3.x);
        acc.y += (v0.y + v1.y) + (v2.y + v3.y);
        acc.z += (v0.z + v1.z) + (v2.z + v3.z);
        acc.w += (v0.w + v1.w) + (v2.w + v3.w);
    }
    for (; i < deg; i++) {
        int s = lst[i];
        float4 v = *reinterpret_cast<const float4*>(x + (size_t)s * IN_CH + c);
        acc.x += v.x; acc.y += v.y; acc.z += v.z; acc.w += v.w;
    }
    *reinterpret_cast<float4*>(g_h1 + (size_t)n * IN_CH + c) = acc;
}

// ---------------------------------------------------------------------------
// Fused hop2-gather + f32x2 GEMM + bias.
// Stage x,h1 (k rows 0..127); GATHER h2 from g_h1 into k rows 128..191;
// then mainloop identical to the 127.4us version:
// Block: 256 threads, 64 nodes x 128 outs, 3 blocks/SM (smem 52KB).
// Thread: 4 node-pairs x 4 outs (16 f32x2 acc).
// ---------------------------------------------------------------------------
#define F2_PITCH 68   // 68 floats = 272 B, 16B-multiple for LDS.128
#define NODES_PER_BLK 64
#define GEMM_THREADS 256
#define GEMM_SMEM_BYTES (F_TOT * F2_PITCH * (int)sizeof(float))

static __device__ __forceinline__ unsigned long long pk(float lo, float hi) {
    unsigned long long r;
    asm("mov.b64 %0, {%1, %2};" : "=l"(r) : "f"(lo), "f"(hi));
    return r;
}
static __device__ __forceinline__ void upk(unsigned long long v, float& lo, float& hi) {
    asm("mov.b64 {%0, %1}, %2;" : "=f"(lo), "=f"(hi) : "l"(v));
}
static __device__ __forceinline__ void ffma2(unsigned long long& d,
                                             unsigned long long a,
                                             unsigned long long b) {
    asm("fma.rn.f32x2 %0, %1, %2, %0;" : "+l"(d) : "l"(a), "l"(b));
}

__global__ __launch_bounds__(GEMM_THREADS, 3)
void gemm_fused_kernel(const float* __restrict__ x,
                       const float* __restrict__ b,
                       float* __restrict__ out) {
    extern __shared__ float fs2[];          // [192][68]: fs2[k*68 + n_local]

    const int tid  = threadIdx.x;
    const int base = blockIdx.x * NODES_PER_BLK;

    // Stage x and h1 (k rows 0..127): consecutive tid -> consecutive k.
    for (int i = tid; i < NODES_PER_BLK * 2 * IN_CH; i += GEMM_THREADS) {
        int n = i >> 7;            // /128
        int k = i & 127;
        int node = base + n;
        if (node >= N_NODES) node = N_NODES - 1;   // clamp; store is guarded
        float v = (k < IN_CH) ? x[(size_t)node * IN_CH + k]
                              : g_h1[(size_t)node * IN_CH + (k - IN_CH)];
        fs2[k * F2_PITCH + n] = v;
    }

    // Fused hop-2 gather: h2[node] from g_h1 -> k rows 128..191.
    // 16 thread-slots per node, one float4 channel group each.
    for (int slot = tid; slot < NODES_PER_BLK * 16; slot += GEMM_THREADS) {
        int n = slot >> 4;
        int c = (slot & 15) << 2;
        int node = base + n;
        float4 acc = make_float4(0.f, 0.f, 0.f, 0.f);
        if (node < N_NODES) {
            int deg = g_cnt[node];
            if (deg > MAX_DEG) deg = MAX_DEG;
            const int* lst = g_srcs + node * MAX_DEG;
            int i = 0;
            for (; i + 4 <= deg; i += 4) {
                int s0 = lst[i], s1 = lst[i + 1], s2 = lst[i + 2], s3 = lst[i + 3];
                float4 v0 = *reinterpret_cast<const float4*>(g_h1 + (size_t)s0 * IN_CH + c);
                float4 v1 = *reinterpret_cast<const float4*>(g_h1 + (size_t)s1 * IN_CH + c);
                float4 v2 = *reinterpret_cast<const float4*>(g_h1 + (size_t)s2 * IN_CH + c);
                float4 v3 = *reinterpret_cast<const float4*>(g_h1 + (size_t)s3 * IN_CH + c);
                acc.x += (v0.x + v1.x) + (v2.x + v3.x);
                acc.y += (v0.y + v1.y) + (v2.y + v3.y);
                acc.z += (v0.z + v1.z) + (v2.z + v3.z);
                acc.w += (v0.w + v1.w) + (v2.w + v3.w);
            }
            for (; i < deg; i++) {
                int s = lst[i];
                float4 v = *reinterpret_cast<const float4*>(g_h1 + (size_t)s * IN_CH + c);
                acc.x += v.x; acc.y += v.y; acc.z += v.z; acc.w += v.w;
            }
        }
        int kb = 2 * IN_CH + c;     // k rows 128..191
        fs2[(kb + 0) * F2_PITCH + n] = acc.x;
        fs2[(kb + 1) * F2_PITCH + n] = acc.y;
        fs2[(kb + 2) * F2_PITCH + n] = acc.z;
        fs2[(kb + 3) * F2_PITCH + n] = acc.w;
    }
    __syncthreads();

    const int to = tid & 31;   // outs [to*4, to*4+4)
    const int w  = tid >> 5;   // warp id: node pairs [w*4, w*4+4)  (8 warps)

    unsigned long long acc[4][4];  // [pair j][out o]
    {
        float4 bias = *reinterpret_cast<const float4*>(b + to * 4);
        unsigned long long b0 = pk(bias.x, bias.x), b1 = pk(bias.y, bias.y);
        unsigned long long b2 = pk(bias.z, bias.z), b3 = pk(bias.w, bias.w);
        #pragma unroll
        for (int j = 0; j < 4; j++) {
            acc[j][0] = b0; acc[j][1] = b1; acc[j][2] = b2; acc[j][3] = b3;
        }
    }

    const float* wrow = g_Wt + to * 4;         // this thread's 4 weights per k
    const float* frow0 = fs2 + w * 8;          // this warp's 8 nodes (4 pairs)
    #pragma unroll 4
    for (int k = 0; k < F_TOT; k++) {
        // Weights: one LDG.128 (same 512B across all warps -> L1-hot)
        float4 w4 = *reinterpret_cast<const float4*>(wrow + (size_t)k * OUT_CH);
        unsigned long long wd0 = pk(w4.x, w4.x);
        unsigned long long wd1 = pk(w4.y, w4.y);
        unsigned long long wd2 = pk(w4.z, w4.z);
        unsigned long long wd3 = pk(w4.w, w4.w);
        // Features: 4 pairs = 32B via 2x LDS.128 broadcast (16B-aligned)
        const float* frow = frow0 + k * F2_PITCH;
        ulonglong2 fa = *reinterpret_cast<const ulonglong2*>(frow);      // pairs 0,1
        ulonglong2 fb = *reinterpret_cast<const ulonglong2*>(frow + 4);  // pairs 2,3
        ffma2(acc[0][0], fa.x, wd0); ffma2(acc[0][1], fa.x, wd1);
        ffma2(acc[0][2], fa.x, wd2); ffma2(acc[0][3], fa.x, wd3);
        ffma2(acc[1][0], fa.y, wd0); ffma2(acc[1][1], fa.y, wd1);
        ffma2(acc[1][2], fa.y, wd2); ffma2(acc[1][3], fa.y, wd3);
        ffma2(acc[2][0], fb.x, wd0); ffma2(acc[2][1], fb.x, wd1);
        ffma2(acc[2][2], fb.x, wd2); ffma2(acc[2][3], fb.x, wd3);
        ffma2(acc[3][0], fb.y, wd0); ffma2(acc[3][1], fb.y, wd1);
        ffma2(acc[3][2], fb.y, wd2); ffma2(acc[3][3], fb.y, wd3);
    }

    #pragma unroll
    for (int j = 0; j < 4; j++) {
        float lo0, hi0, lo1, hi1, lo2, hi2, lo3, hi3;
        upk(acc[j][0], lo0, hi0); upk(acc[j][1], lo1, hi1);
        upk(acc[j][2], lo2, hi2); upk(acc[j][3], lo3, hi3);
        int n0 = base + (w * 4 + j) * 2;
        if (n0 < N_NODES) {
            *reinterpret_cast<float4*>(out + (size_t)n0 * OUT_CH + to * 4) =
                make_float4(lo0, lo1, lo2, lo3);
        }
        if (n0 + 1 < N_NODES) {
            *reinterpret_cast<float4*>(out + (size_t)(n0 + 1) * OUT_CH + to * 4) =
                make_float4(hi0, hi1, hi2, hi3);
        }
    }
}

// ---------------------------------------------------------------------------
// Launch: zero+detect+transpose -> fill -> gather1 -> fused gemm  (4 launches)
// ---------------------------------------------------------------------------
extern "C" void kernel_launch(void* const* d_in, const int* in_sizes, int n_in,
                              void* d_out, int out_size) {
    const float*  x   = (const float*)d_in[0];
    const int*    ei  = (const int*)d_in[1];
    const float*  W   = (const float*)d_in[2];
    const float*  b   = (const float*)d_in[3];
    float*        out = (float*)d_out;

    cudaFuncSetAttribute(gemm_fused_kernel,
                         cudaFuncAttributeMaxDynamicSharedMemorySize,
                         GEMM_SMEM_BYTES);

    zero_detect_transpose_kernel<<<(N_NODES + 1023) / 1024, 1024>>>(ei, W);
    fill_kernel<<<(N_EDGES + 255) / 256, 256>>>(ei);

    const int gthreads = N_NODES * 16;
    gather_kernel<<<(gthreads + 255) / 256, 256>>>(x);

    const int gemm_blocks = (N_NODES + NODES_PER_BLK - 1) / NODES_PER_BLK;
    gemm_fused_kernel<<<gemm_blocks, GEMM_THREADS, GEMM_SMEM_BYTES>>>(x, b, out);
}